// round 13
// baseline (speedup 1.0000x reference)
#include <cuda_runtime.h>
#include <math.h>

#define B_    64
#define H_    32
#define KVH_  8
#define D_    128
#define BS_   128
#define NB_   1024
#define G_    4
#define HD_   (H_*D_)     // 4096
#define KVHD_ (KVH_*D_)   // 1024
#define SCALE_ 0.08838834764831845f

#define CHTOK 32            // tokens per chunk
#define CH4   (CHTOK*32)    // float4 per chunk (32 rows x 32 float4)
#define NSTG  3             // pipeline ring buffers
#define MAXBLK 32           // max blocks per sequence (dataset: 16)

#define CP_ASYNC_CG(dst_u32, src_ptr) \
    asm volatile("cp.async.cg.shared.global [%0], [%1], 16;" :: "r"(dst_u32), "l"(src_ptr) : "memory")
#define CP_ASYNC_COMMIT() asm volatile("cp.async.commit_group;" ::: "memory")
#define CP_ASYNC_WAIT2()  asm volatile("cp.async.wait_group 2;" ::: "memory")
#define CP_ASYNC_WAIT1()  asm volatile("cp.async.wait_group 1;" ::: "memory")
#define CP_ASYNC_WAIT0()  asm volatile("cp.async.wait_group 0;" ::: "memory")

extern __shared__ char smem_raw[];

// smem: [0,48K) ring | 48K q4(2K) | 50K p(2K) | 52K control block
#define SM_Q4    (NSTG*CH4*16)          // 49152
#define SM_P     (SM_Q4 + 2048)         // 51200
#define SM_CTL   (SM_P + 2048)          // 53248
#define SMEM_BYTES (SM_CTL + 4*MAXBLK*4 + 64)

// ---------------------------------------------------------------------------
// Fused kernel, PER-WARP pipelines: warp w owns token rows w*8..w*8+7 of
// every chunk — it stages them itself (private cp.async groups), computes
// QK/PV on them, and never synchronizes with other warps per chunk. CTA-wide
// barriers only at softmax (2 per block) + epilogue. This decouples warp
// progress so load-completion jitter no longer gates chip-wide issue.
// ---------------------------------------------------------------------------
__global__ void __launch_bounds__(128, 4) fused_attn_kernel(
    const float* __restrict__ query,
    const float* __restrict__ kc,
    const float* __restrict__ vc,
    const float* __restrict__ knew,
    const float* __restrict__ vnew,
    const int*   __restrict__ block_list,
    const int*   __restrict__ block_groups,
    const float* __restrict__ block_bias,
    const int*   __restrict__ bidx,
    const int*   __restrict__ boff,
    float*       __restrict__ out)
{
    const int kvh = blockIdx.x;     // fast dim: same-seq CTAs id-adjacent
    const int s   = blockIdx.y;     // sequence
    const int tid = threadIdx.x;
    const int w   = tid >> 5;
    const int l   = tid & 31;

    float4* tile = (float4*)smem_raw;                 // ring: 3 x 1024 float4
    float4* q4   = (float4*)(smem_raw + SM_Q4);       // 128 float4
    float*  p    = (float*) (smem_raw + SM_P);        // 512 floats
    int*  ns_sh  = (int*)   (smem_raw + SM_CTL);
    int*  cbs_sh = ns_sh + MAXBLK;
    int*  psh_sh = cbs_sh + MAXBLK;
    int*  posh_sh= psh_sh + MAXBLK;
    float* cfsh  = (float*)(posh_sh + MAXBLK);        // 4
    float* Lsh   = cfsh + 4;                          // 4
    int*  cnt_sh = (int*)(Lsh + 4);

    // ---- setup (warp 0): compact seq's block list, cache ids, patch info ----
    if (w == 0) {
        int count = 0;
        for (int base = 0; base < NB_; base += 32) {
            int nn = base + l;
            int match = (__ldg(block_groups + nn) == s);
            unsigned mask = __ballot_sync(0xFFFFFFFFu, match);
            int pos = count + __popc(mask & ((1u << l) - 1u));
            if (match && pos < MAXBLK) ns_sh[pos] = nn;
            count += __popc(mask);
        }
        if (count > MAXBLK) count = MAXBLK;
        if (l == 0) *cnt_sh = count;
        __syncwarp();
        if (l < count) cbs_sh[l] = __ldg(block_list + ns_sh[l]);
        __syncwarp();
        if (l < count) {
            int pps = -1;
            int cbv = cbs_sh[l];
            for (int s2 = 0; s2 < B_; s2++)
                if (__ldg(bidx + s2) == cbv) pps = s2;
            psh_sh[l]  = pps;
            posh_sh[l] = (pps >= 0) ? __ldg(boff + pps) : -1;
        }
    }
    // ---- other warps: load q (scaled) meanwhile ----
    {
        float4 qv = ((const float4*)(query + (long)s * HD_ + (kvh * G_ + w) * D_))[l];
        qv.x *= SCALE_; qv.y *= SCALE_; qv.z *= SCALE_; qv.w *= SCALE_;
        q4[tid] = qv;
    }
    __syncthreads();

    const int m = *cnt_sh;
    const int T = 8 * m;                 // total chunks in the stream

    const unsigned sbase = (unsigned)__cvta_generic_to_shared(tile);

    // -- per-warp stage of chunk j: warp w loads ITS 8 token rows only.
    //    row r = w*8+rr (512B contiguous, lane = float4 column, swizzled) --
    auto issue_chunk = [&](int j) {
        int jb = j >> 3;
        const float* basep = ((j >> 2) & 1) ? vc : kc;
        const float* src = basep + (long)cbs_sh[jb] * BS_ * KVHD_ + kvh * D_
                         + (long)((j & 3) * CHTOK) * KVHD_;
        const int bi = j % NSTG;
        #pragma unroll
        for (int rr = 0; rr < 8; rr++) {
            int r = w * 8 + rr;
            unsigned dst = sbase + (unsigned)((bi * CH4 + r * 32 + (l ^ (r & 7))) * 16);
            CP_ASYNC_CG(dst, (const float4*)(src + (long)r * KVHD_) + l);
        }
        CP_ASYNC_COMMIT();
    };

    // per-warp wait so this warp's rows of chunks 0..j are complete
    auto wait_for = [&](int j) {
        if      (j < T - 2) { CP_ASYNC_WAIT2(); }
        else if (j == T - 2){ CP_ASYNC_WAIT1(); }
        else                { CP_ASYNC_WAIT0(); }
    };

    // ---- prologue (per warp) ----
    if (T > 0) issue_chunk(0);
    if (T > 1) issue_chunk(1);
    if (T > 2) issue_chunk(2);

    // QK lane mapping: token = w*8+(l&7), quarter = l>>3 (conflict-free)
    const int tl = w * 8 + (l & 7);
    const int qq = l >> 3;
    const int sw = tl & 7;

    float4 o0 = make_float4(0.f,0.f,0.f,0.f), o1 = o0, o2 = o0, o3 = o0;
    float M = -3.4e38f, L = 0.f;

    for (int b = 0; b < m; b++) {
        const int nid = ns_sh[b];
        const int pps = psh_sh[b];
        const int ppo = posh_sh[b];

        // ===== K chunks (per-warp, no CTA barriers) =====
        #pragma unroll
        for (int c = 0; c < 4; c++) {
            const int j  = b * 8 + c;
            const int bi = j % NSTG;
            wait_for(j);
            // patch new K row if it lives in this warp's rows of this chunk
            if (pps >= 0 && (ppo >> 5) == c && ((ppo & 31) >> 3) == w) {
                int lr = ppo & 31;
                tile[bi * CH4 + lr * 32 + (l ^ (lr & 7))] =
                    ((const float4*)(knew + (long)(pps * KVH_ + kvh) * D_))[l];
                __syncwarp();
            }
            {   // QK on this warp's 8 tokens
                const float4* kb = tile + bi * CH4 + tl * 32;
                float a0 = 0.f, a1 = 0.f, a2 = 0.f, a3 = 0.f;
                #pragma unroll
                for (int jj = 0; jj < 8; jj++) {
                    float4 k  = kb[(qq * 8 + jj) ^ sw];
                    float4 qa = q4[qq * 8 + jj];
                    float4 qb = q4[32 + qq * 8 + jj];
                    float4 qc = q4[64 + qq * 8 + jj];
                    float4 qd = q4[96 + qq * 8 + jj];
                    a0 += k.x*qa.x + k.y*qa.y + k.z*qa.z + k.w*qa.w;
                    a1 += k.x*qb.x + k.y*qb.y + k.z*qb.z + k.w*qb.w;
                    a2 += k.x*qc.x + k.y*qc.y + k.z*qc.z + k.w*qc.w;
                    a3 += k.x*qd.x + k.y*qd.y + k.z*qd.z + k.w*qd.w;
                }
                a0 += __shfl_xor_sync(0xFFFFFFFFu, a0, 8);
                a0 += __shfl_xor_sync(0xFFFFFFFFu, a0, 16);
                a1 += __shfl_xor_sync(0xFFFFFFFFu, a1, 8);
                a1 += __shfl_xor_sync(0xFFFFFFFFu, a1, 16);
                a2 += __shfl_xor_sync(0xFFFFFFFFu, a2, 8);
                a2 += __shfl_xor_sync(0xFFFFFFFFu, a2, 16);
                a3 += __shfl_xor_sync(0xFFFFFFFFu, a3, 8);
                a3 += __shfl_xor_sync(0xFFFFFFFFu, a3, 16);
                if (qq == 0) {
                    int tok = c * CHTOK + tl;
                    p[0*BS_ + tok] = a0;
                    p[1*BS_ + tok] = a1;
                    p[2*BS_ + tok] = a2;
                    p[3*BS_ + tok] = a3;
                }
            }
            if (j + 3 < T) issue_chunk(j + 3);
        }

        __syncthreads();   // all warps' logits for this block are in p

        // ===== softmax + online merge: warp w owns head g = w =====
        {
            const float* bb = block_bias + (long)nid * BS_;
            float v0 = p[w*BS_ + l]      + bb[l];
            float v1 = p[w*BS_ + l + 32] + bb[l + 32];
            float v2 = p[w*BS_ + l + 64] + bb[l + 64];
            float v3 = p[w*BS_ + l + 96] + bb[l + 96];
            float mb = fmaxf(fmaxf(v0, v1), fmaxf(v2, v3));
            #pragma unroll
            for (int off = 16; off; off >>= 1)
                mb = fmaxf(mb, __shfl_xor_sync(0xFFFFFFFFu, mb, off));
            float Mn = fmaxf(M, mb);
            float e0 = __expf(v0 - Mn);
            float e1 = __expf(v1 - Mn);
            float e2 = __expf(v2 - Mn);
            float e3 = __expf(v3 - Mn);
            p[w*BS_ + l]      = e0;
            p[w*BS_ + l + 32] = e1;
            p[w*BS_ + l + 64] = e2;
            p[w*BS_ + l + 96] = e3;
            float sloc = e0 + e1 + e2 + e3;
            #pragma unroll
            for (int off = 16; off; off >>= 1)
                sloc += __shfl_xor_sync(0xFFFFFFFFu, sloc, off);
            float cf = __expf(M - Mn);     // 0 on first block (underflow)
            L = L * cf + sloc;
            M = Mn;
            if (l == 0) cfsh[w] = cf;
        }
        __syncthreads();   // exp'd p + cfsh visible to all warps

        // rescale accumulators by each head's carry factor
        {
            float c0 = cfsh[0], c1 = cfsh[1], c2 = cfsh[2], c3 = cfsh[3];
            o0.x*=c0; o0.y*=c0; o0.z*=c0; o0.w*=c0;
            o1.x*=c1; o1.y*=c1; o1.z*=c1; o1.w*=c1;
            o2.x*=c2; o2.y*=c2; o2.z*=c2; o2.w*=c2;
            o3.x*=c3; o3.y*=c3; o3.z*=c3; o3.w*=c3;
        }

        // ===== V chunks (per-warp, no CTA barriers) =====
        #pragma unroll
        for (int c = 0; c < 4; c++) {
            const int j  = b * 8 + 4 + c;
            const int bi = j % NSTG;
            wait_for(j);
            if (pps >= 0 && (ppo >> 5) == c && ((ppo & 31) >> 3) == w) {
                int lr = ppo & 31;
                tile[bi * CH4 + lr * 32 + (l ^ (lr & 7))] =
                    ((const float4*)(vnew + (long)(pps * KVH_ + kvh) * D_))[l];
                __syncwarp();
            }
            {   // PV: this warp's 8 tokens, lane = d4 column
                const float4* vb = tile + bi * CH4;
                #pragma unroll
                for (int i = 0; i < 8; i++) {
                    int tlo = w * 8 + i;
                    int tok = c * CHTOK + tlo;
                    float4 v = vb[tlo * 32 + (l ^ (tlo & 7))];
                    float p0 = p[tok];
                    float p1 = p[BS_ + tok];
                    float p2 = p[2*BS_ + tok];
                    float p3 = p[3*BS_ + tok];
                    o0.x += p0*v.x; o0.y += p0*v.y; o0.z += p0*v.z; o0.w += p0*v.w;
                    o1.x += p1*v.x; o1.y += p1*v.y; o1.z += p1*v.z; o1.w += p1*v.w;
                    o2.x += p2*v.x; o2.y += p2*v.y; o2.z += p2*v.z; o2.w += p2*v.w;
                    o3.x += p3*v.x; o3.y += p3*v.y; o3.z += p3*v.z; o3.w += p3*v.w;
                }
            }
            if (j + 3 < T) issue_chunk(j + 3);
        }
        // NOTE: p is re-written only after next block's K compute + barrier,
        // and each warp's V reads of block b happen before its next K compute
        // reaches the barrier -> the post-K __syncthreads orders p reuse.
    }

    // ===== epilogue: cross-warp reduce, normalize, store =====
    if (l == 0) Lsh[w] = L;
    __syncthreads();   // all warps done streaming; ring safe to reuse
    {
        float4* red = tile;   // [warp][g][d4] = 4*4*32 float4 = 8KB
        red[(w * 4 + 0) * 32 + l] = o0;
        red[(w * 4 + 1) * 32 + l] = o1;
        red[(w * 4 + 2) * 32 + l] = o2;
        red[(w * 4 + 3) * 32 + l] = o3;
        __syncthreads();
        // thread = (g = w, d4 = l)
        float4 r0v = red[(0 * 4 + w) * 32 + l];
        float4 r1v = red[(1 * 4 + w) * 32 + l];
        float4 r2v = red[(2 * 4 + w) * 32 + l];
        float4 r3v = red[(3 * 4 + w) * 32 + l];
        float inv = 1.f / fmaxf(Lsh[w], 1e-37f);
        float4 sum;
        sum.x = ((r0v.x + r1v.x) + (r2v.x + r3v.x)) * inv;
        sum.y = ((r0v.y + r1v.y) + (r2v.y + r3v.y)) * inv;
        sum.z = ((r0v.z + r1v.z) + (r2v.z + r3v.z)) * inv;
        sum.w = ((r0v.w + r1v.w) + (r2v.w + r3v.w)) * inv;
        ((float4*)(out + ((long)s * H_ + kvh * G_ + w) * D_))[l] = sum;
    }
}

// ---------------------------------------------------------------------------
extern "C" void kernel_launch(void* const* d_in, const int* in_sizes, int n_in,
                              void* d_out, int out_size) {
    const float* query        = (const float*)d_in[0];
    const float* knew         = (const float*)d_in[1];
    const float* vnew         = (const float*)d_in[2];
    const float* key_cache    = (const float*)d_in[3];
    const float* value_cache  = (const float*)d_in[4];
    const int*   block_list   = (const int*)d_in[5];
    const int*   block_groups = (const int*)d_in[6];
    // d_in[7] = block_mapping (one-hot) -- implied by block_groups
    const float* block_bias   = (const float*)d_in[8];
    const int*   bidx         = (const int*)d_in[9];
    const int*   boff         = (const int*)d_in[10];
    float*       out          = (float*)d_out;

    cudaFuncSetAttribute(fused_attn_kernel,
                         cudaFuncAttributeMaxDynamicSharedMemorySize, SMEM_BYTES);

    // grid = (KVH, B): kvh fastest so same-seq CTAs are id-adjacent
    fused_attn_kernel<<<dim3(KVH_, B_), 128, SMEM_BYTES>>>(
        query, key_cache, value_cache, knew, vnew,
        block_list, block_groups, block_bias, bidx, boff, out);
}

// round 14
// speedup vs baseline: 1.0997x; 1.0997x over previous
#include <cuda_runtime.h>
#include <math.h>

#define B_    64
#define H_    32
#define KVH_  8
#define D_    128
#define BS_   128
#define NB_   1024
#define G_    4
#define HD_   (H_*D_)     // 4096
#define KVHD_ (KVH_*D_)   // 1024
#define SCALE_ 0.08838834764831845f

#define CHTOK 32            // tokens per chunk
#define CH4   (CHTOK*32)    // float4 per chunk (32 rows x 32 float4)
#define NSTG  3             // pipeline ring buffers
#define MAXBLK 32           // max blocks per sequence (dataset: 16)

#define CP_ASYNC_CG(dst_u32, src_ptr) \
    asm volatile("cp.async.cg.shared.global [%0], [%1], 16;" :: "r"(dst_u32), "l"(src_ptr) : "memory")
#define CP_ASYNC_COMMIT() asm volatile("cp.async.commit_group;" ::: "memory")
#define CP_ASYNC_WAIT2()  asm volatile("cp.async.wait_group 2;" ::: "memory")
#define CP_ASYNC_WAIT1()  asm volatile("cp.async.wait_group 1;" ::: "memory")
#define CP_ASYNC_WAIT0()  asm volatile("cp.async.wait_group 0;" ::: "memory")

extern __shared__ char smem_raw[];

// smem: [0,48K) ring | 48K q4(2K) | 50K p(2K) | 52K control block
#define SM_Q4    (NSTG*CH4*16)          // 49152
#define SM_P     (SM_Q4 + 2048)         // 51200
#define SM_CTL   (SM_P + 2048)          // 53248
#define SMEM_BYTES (SM_CTL + 4*MAXBLK*4 + 64)

// ---------------------------------------------------------------------------
// Fused kernel: one CTA per (kvh, seq); CTA-wide 3-stage cp.async ring with
// online-softmax merge (the R11 structure = best so far), with a
// LATENCY-PARALLEL prologue: all index loads burst first (MLP=32), then
// register-only ballot compaction + shfl-based patch search. This removes
// the ~10us serial-LDG chain that idled the whole chip at wave start.
// ---------------------------------------------------------------------------
__global__ void __launch_bounds__(128, 4) fused_attn_kernel(
    const float* __restrict__ query,
    const float* __restrict__ kc,
    const float* __restrict__ vc,
    const float* __restrict__ knew,
    const float* __restrict__ vnew,
    const int*   __restrict__ block_list,
    const int*   __restrict__ block_groups,
    const float* __restrict__ block_bias,
    const int*   __restrict__ bidx,
    const int*   __restrict__ boff,
    float*       __restrict__ out)
{
    const int kvh = blockIdx.x;     // fast dim: same-seq CTAs id-adjacent
    const int s   = blockIdx.y;     // sequence
    const int tid = threadIdx.x;
    const int w   = tid >> 5;
    const int l   = tid & 31;

    float4* tile = (float4*)smem_raw;                 // ring: 3 x 1024 float4
    float4* q4   = (float4*)(smem_raw + SM_Q4);       // 128 float4
    float*  p    = (float*) (smem_raw + SM_P);        // 512 floats
    int*  ns_sh  = (int*)   (smem_raw + SM_CTL);
    int*  cbs_sh = ns_sh + MAXBLK;
    int*  psh_sh = cbs_sh + MAXBLK;
    int*  posh_sh= psh_sh + MAXBLK;
    float* cfsh  = (float*)(posh_sh + MAXBLK);        // 4
    float* Lsh   = cfsh + 4;                          // 4
    int*  cnt_sh = (int*)(Lsh + 4);

    // ---- setup (warp 0): latency-parallel scan ----
    if (w == 0) {
        // 1) burst: all index loads in flight at once (independent LDGs)
        int vals[32];
        #pragma unroll
        for (int ii = 0; ii < 32; ii++)
            vals[ii] = __ldg(block_groups + ii * 32 + l);
        int b0 = __ldg(bidx + l);
        int b1 = __ldg(bidx + 32 + l);
        int f0 = __ldg(boff + l);
        int f1 = __ldg(boff + 32 + l);

        // 2) register-only ballot compaction (deterministic order)
        int count = 0;
        #pragma unroll
        for (int ii = 0; ii < 32; ii++) {
            int match = (vals[ii] == s);
            unsigned mask = __ballot_sync(0xFFFFFFFFu, match);
            int pos = count + __popc(mask & ((1u << l) - 1u));
            if (match && pos < MAXBLK) ns_sh[pos] = ii * 32 + l;
            count += __popc(mask);
        }
        if (count > MAXBLK) count = MAXBLK;
        if (l == 0) *cnt_sh = count;
        __syncwarp();

        // 3) cache block ids (single dependent LDG round)
        int cb = (l < count) ? __ldg(block_list + ns_sh[l]) : -1;
        if (l < count) cbs_sh[l] = cb;
        __syncwarp();

        // 4) patch search via ballot+clz+shfl (last match = highest index)
        for (int e = 0; e < count; e++) {
            int cbv = __shfl_sync(0xFFFFFFFFu, cb, e);
            unsigned m0 = __ballot_sync(0xFFFFFFFFu, b0 == cbv);
            unsigned m1 = __ballot_sync(0xFFFFFFFFu, b1 == cbv);
            int pps = -1;
            if (m1)      pps = 32 + (31 - __clz(m1));
            else if (m0) pps = 31 - __clz(m0);
            int v0 = __shfl_sync(0xFFFFFFFFu, f0, pps & 31);
            int v1 = __shfl_sync(0xFFFFFFFFu, f1, pps & 31);
            int po = (pps < 0) ? -1 : ((pps >= 32) ? v1 : v0);
            if (l == 0) { psh_sh[e] = pps; posh_sh[e] = po; }
        }
    }
    // ---- other warps: load q (scaled) meanwhile ----
    {
        float4 qv = ((const float4*)(query + (long)s * HD_ + (kvh * G_ + w) * D_))[l];
        qv.x *= SCALE_; qv.y *= SCALE_; qv.z *= SCALE_; qv.w *= SCALE_;
        q4[tid] = qv;
    }
    __syncthreads();

    const int m = *cnt_sh;
    const int T = 8 * m;                 // total chunks in the stream

    const unsigned sbase = (unsigned)__cvta_generic_to_shared(tile);
    const int j_st = tid & 31;           // staging float4 column
    const int r0   = tid >> 5;           // staging row quarter

    // -- issue global chunk j: block j>>3, phase (j>>2)&1 (0=K,1=V), ck j&3 --
    auto issue_chunk = [&](int j) {
        int jb = j >> 3;
        const float* basep = ((j >> 2) & 1) ? vc : kc;
        const float* src = basep + (long)cbs_sh[jb] * BS_ * KVHD_ + kvh * D_
                         + (long)((j & 3) * CHTOK) * KVHD_;
        const int bi = j % NSTG;
        #pragma unroll
        for (int rr = 0; rr < 8; rr++) {
            int r = rr * 4 + r0;   // local row 0..31
            unsigned dst = sbase + (unsigned)((bi * CH4 + r * 32 + (j_st ^ (r & 7))) * 16);
            CP_ASYNC_CG(dst, (const float4*)(src + (long)r * KVHD_) + j_st);
        }
        CP_ASYNC_COMMIT();
    };

    // chunks 0..j complete (drain-correct at stream end)
    auto wait_for = [&](int j) {
        if      (j < T - 2) { CP_ASYNC_WAIT2(); }
        else if (j == T - 2){ CP_ASYNC_WAIT1(); }
        else                { CP_ASYNC_WAIT0(); }
    };

    // ---- prologue ----
    if (T > 0) issue_chunk(0);
    if (T > 1) issue_chunk(1);
    if (T > 2) issue_chunk(2);

    // QK lane mapping: token = w*8+(l&7), quarter = l>>3 (conflict-free)
    const int tl = w * 8 + (l & 7);
    const int qq = l >> 3;
    const int sw = tl & 7;

    // online state: accumulators (all warps), stats M/L (warp w = head w)
    float4 o0 = make_float4(0.f,0.f,0.f,0.f), o1 = o0, o2 = o0, o3 = o0;
    float M = -3.4e38f, L = 0.f;

    for (int b = 0; b < m; b++) {
        const int nid = ns_sh[b];
        const int pps = psh_sh[b];
        const int ppo = posh_sh[b];

        // ===== K chunks =====
        #pragma unroll
        for (int c = 0; c < 4; c++) {
            const int j  = b * 8 + c;
            const int bi = j % NSTG;
            wait_for(j);
            __syncthreads();
            if (pps >= 0 && (ppo >> 5) == c) {          // patch new K row
                if (tid < 32) {
                    int lr = ppo & 31;
                    tile[bi * CH4 + lr * 32 + (tid ^ (lr & 7))] =
                        ((const float4*)(knew + (long)(pps * KVH_ + kvh) * D_))[tid];
                }
                __syncthreads();
            }
            {   // QK on this chunk
                const float4* kb = tile + bi * CH4 + tl * 32;
                float a0 = 0.f, a1 = 0.f, a2 = 0.f, a3 = 0.f;
                #pragma unroll
                for (int jj = 0; jj < 8; jj++) {
                    float4 k  = kb[(qq * 8 + jj) ^ sw];
                    float4 qa = q4[qq * 8 + jj];
                    float4 qb = q4[32 + qq * 8 + jj];
                    float4 qc = q4[64 + qq * 8 + jj];
                    float4 qd = q4[96 + qq * 8 + jj];
                    a0 += k.x*qa.x + k.y*qa.y + k.z*qa.z + k.w*qa.w;
                    a1 += k.x*qb.x + k.y*qb.y + k.z*qb.z + k.w*qb.w;
                    a2 += k.x*qc.x + k.y*qc.y + k.z*qc.z + k.w*qc.w;
                    a3 += k.x*qd.x + k.y*qd.y + k.z*qd.z + k.w*qd.w;
                }
                a0 += __shfl_xor_sync(0xFFFFFFFFu, a0, 8);
                a0 += __shfl_xor_sync(0xFFFFFFFFu, a0, 16);
                a1 += __shfl_xor_sync(0xFFFFFFFFu, a1, 8);
                a1 += __shfl_xor_sync(0xFFFFFFFFu, a1, 16);
                a2 += __shfl_xor_sync(0xFFFFFFFFu, a2, 8);
                a2 += __shfl_xor_sync(0xFFFFFFFFu, a2, 16);
                a3 += __shfl_xor_sync(0xFFFFFFFFu, a3, 8);
                a3 += __shfl_xor_sync(0xFFFFFFFFu, a3, 16);
                if (qq == 0) {
                    int tok = c * CHTOK + tl;
                    p[0*BS_ + tok] = a0;
                    p[1*BS_ + tok] = a1;
                    p[2*BS_ + tok] = a2;
                    p[3*BS_ + tok] = a3;
                }
            }
            __syncthreads();
            if (j + 3 < T) issue_chunk(j + 3);
        }

        // ===== softmax + online merge: warp w owns head g = w =====
        {
            const float* bb = block_bias + (long)nid * BS_;
            float v0 = p[w*BS_ + l]      + bb[l];
            float v1 = p[w*BS_ + l + 32] + bb[l + 32];
            float v2 = p[w*BS_ + l + 64] + bb[l + 64];
            float v3 = p[w*BS_ + l + 96] + bb[l + 96];
            float mb = fmaxf(fmaxf(v0, v1), fmaxf(v2, v3));
            #pragma unroll
            for (int off = 16; off; off >>= 1)
                mb = fmaxf(mb, __shfl_xor_sync(0xFFFFFFFFu, mb, off));
            float Mn = fmaxf(M, mb);
            float e0 = __expf(v0 - Mn);
            float e1 = __expf(v1 - Mn);
            float e2 = __expf(v2 - Mn);
            float e3 = __expf(v3 - Mn);
            p[w*BS_ + l]      = e0;
            p[w*BS_ + l + 32] = e1;
            p[w*BS_ + l + 64] = e2;
            p[w*BS_ + l + 96] = e3;
            float sloc = e0 + e1 + e2 + e3;
            #pragma unroll
            for (int off = 16; off; off >>= 1)
                sloc += __shfl_xor_sync(0xFFFFFFFFu, sloc, off);
            float cf = __expf(M - Mn);     // 0 on first block (underflow)
            L = L * cf + sloc;
            M = Mn;
            if (l == 0) cfsh[w] = cf;
        }
        __syncthreads();   // exp'd p + cfsh visible

        // rescale accumulators by each head's carry factor
        {
            float c0 = cfsh[0], c1 = cfsh[1], c2 = cfsh[2], c3 = cfsh[3];
            o0.x*=c0; o0.y*=c0; o0.z*=c0; o0.w*=c0;
            o1.x*=c1; o1.y*=c1; o1.z*=c1; o1.w*=c1;
            o2.x*=c2; o2.y*=c2; o2.z*=c2; o2.w*=c2;
            o3.x*=c3; o3.y*=c3; o3.z*=c3; o3.w*=c3;
        }

        // ===== V chunks =====
        #pragma unroll
        for (int c = 0; c < 4; c++) {
            const int j  = b * 8 + 4 + c;
            const int bi = j % NSTG;
            wait_for(j);
            __syncthreads();
            if (pps >= 0 && (ppo >> 5) == c) {          // patch new V row
                if (tid < 32) {
                    int lr = ppo & 31;
                    tile[bi * CH4 + lr * 32 + (tid ^ (lr & 7))] =
                        ((const float4*)(vnew + (long)(pps * KVH_ + kvh) * D_))[tid];
                }
                __syncthreads();
            }
            {   // PV: warp w handles 8 tokens, lane = d4 column
                const float4* vb = tile + bi * CH4;
                #pragma unroll
                for (int i = 0; i < 8; i++) {
                    int tlo = w * 8 + i;
                    int tok = c * CHTOK + tlo;
                    float4 v = vb[tlo * 32 + (l ^ (tlo & 7))];
                    float p0 = p[tok];
                    float p1 = p[BS_ + tok];
                    float p2 = p[2*BS_ + tok];
                    float p3 = p[3*BS_ + tok];
                    o0.x += p0*v.x; o0.y += p0*v.y; o0.z += p0*v.z; o0.w += p0*v.w;
                    o1.x += p1*v.x; o1.y += p1*v.y; o1.z += p1*v.z; o1.w += p1*v.w;
                    o2.x += p2*v.x; o2.y += p2*v.y; o2.z += p2*v.z; o2.w += p2*v.w;
                    o3.x += p3*v.x; o3.y += p3*v.y; o3.z += p3*v.z; o3.w += p3*v.w;
                }
            }
            __syncthreads();
            if (j + 3 < T) issue_chunk(j + 3);
        }
    }

    // ===== epilogue: cross-warp reduce, normalize, store =====
    if (l == 0) Lsh[w] = L;
    {
        float4* red = tile;   // ring free after final barrier inside loop
        red[(w * 4 + 0) * 32 + l] = o0;
        red[(w * 4 + 1) * 32 + l] = o1;
        red[(w * 4 + 2) * 32 + l] = o2;
        red[(w * 4 + 3) * 32 + l] = o3;
        __syncthreads();
        // thread = (g = w, d4 = l)
        float4 r0v = red[(0 * 4 + w) * 32 + l];
        float4 r1v = red[(1 * 4 + w) * 32 + l];
        float4 r2v = red[(2 * 4 + w) * 32 + l];
        float4 r3v = red[(3 * 4 + w) * 32 + l];
        float inv = 1.f / fmaxf(Lsh[w], 1e-37f);
        float4 sum;
        sum.x = ((r0v.x + r1v.x) + (r2v.x + r3v.x)) * inv;
        sum.y = ((r0v.y + r1v.y) + (r2v.y + r3v.y)) * inv;
        sum.z = ((r0v.z + r1v.z) + (r2v.z + r3v.z)) * inv;
        sum.w = ((r0v.w + r1v.w) + (r2v.w + r3v.w)) * inv;
        ((float4*)(out + ((long)s * H_ + kvh * G_ + w) * D_))[l] = sum;
    }
}

// ---------------------------------------------------------------------------
extern "C" void kernel_launch(void* const* d_in, const int* in_sizes, int n_in,
                              void* d_out, int out_size) {
    const float* query        = (const float*)d_in[0];
    const float* knew         = (const float*)d_in[1];
    const float* vnew         = (const float*)d_in[2];
    const float* key_cache    = (const float*)d_in[3];
    const float* value_cache  = (const float*)d_in[4];
    const int*   block_list   = (const int*)d_in[5];
    const int*   block_groups = (const int*)d_in[6];
    // d_in[7] = block_mapping (one-hot) -- implied by block_groups
    const float* block_bias   = (const float*)d_in[8];
    const int*   bidx         = (const int*)d_in[9];
    const int*   boff         = (const int*)d_in[10];
    float*       out          = (float*)d_out;

    cudaFuncSetAttribute(fused_attn_kernel,
                         cudaFuncAttributeMaxDynamicSharedMemorySize, SMEM_BYTES);

    // grid = (KVH, B): kvh fastest so same-seq CTAs are id-adjacent
    fused_attn_kernel<<<dim3(KVH_, B_), 128, SMEM_BYTES>>>(
        query, key_cache, value_cache, knew, vnew,
        block_list, block_groups, block_bias, bidx, boff, out);
}